// round 8
// baseline (speedup 1.0000x reference)
#include <cuda_runtime.h>
#include <math.h>

// Problem constants
static const int BB = 64;    // batch
static const int SL = 512;   // sequence length
static const int HD = 512;   // hidden
#define NBLK 128             // persistent chain blocks (<=148 SMs -> all resident)
#define XBLK 8               // x-chain blocks

// ------------------- device scratch (no allocations allowed) -------------------
__device__ float g_K1[(size_t)BB * SL * HD];    // key projection, row = b*SL+s
__device__ float g_Q [(size_t)SL * BB * HD];    // query,          row = t*BB+b
__device__ float g_Hs[(size_t)SL * BB * HD];    // h sequence,     row = t*BB+b
__device__ float g_hT[2][HD * BB];              // transposed h (double buffer) [j][b]
__device__ float g_Xs[(size_t)SL * HD];         // x' chain, s_t row per t
__device__ float g_XGall[(size_t)SL * 4 * HD];  // XG[t][gate_row] = s_t@W_ih^T + bias
__device__ float g_bias[4 * HD];                // b_ih + b_hh
__device__ float g_L [(size_t)BB * SL * SL];    // logits fallback scratch

// master-token grid barriers (equality-compared monotonic tokens; replay-safe
// because the final-step barrier is skipped: stale values never equal tok=1..)
__device__ unsigned int g_flags[NBLK];
__device__ unsigned int g_go;
__device__ unsigned int g_xflags[XBLK];
__device__ unsigned int g_xgo;

// ------------------- accurate fast activations (flag-independent) -------------------
__device__ __forceinline__ float sigm_f(float x) {
    float e = __expf(-x);
    return __fdividef(1.0f, 1.0f + e);
}
__device__ __forceinline__ float tanh_f(float x) {
    float e = __expf(2.0f * x);
    return 1.0f - __fdividef(2.0f, e + 1.0f);
}

// packed fp32x2 FMA (FFMA2) -- PTX-only
__device__ __forceinline__ void ffma2(unsigned long long& d, unsigned long long a,
                                      unsigned long long b) {
    asm("fma.rn.f32x2 %0, %1, %2, %0;" : "+l"(d) : "l"(a), "l"(b));
}
// duplicate a float into both halves of a 64-bit pair
__device__ __forceinline__ unsigned long long dup2(float x) {
    unsigned long long r;
    asm("mov.b64 %0, {%1, %1};" : "=l"(r) : "f"(x));
    return r;
}

// ------------------- prologue: Xs[0], bias, transpose h0 -------------------
__global__ void __launch_bounds__(256) prologue_kernel(
    const float* __restrict__ h0, const float* __restrict__ b_in,
    const float* __restrict__ b_ih, const float* __restrict__ b_hh)
{
    int blk = blockIdx.x, tid = threadIdx.x;
    if (blk == 0) {
        for (int i = tid; i < HD; i += 256) g_Xs[i] = sigm_f(b_in[i]);
        for (int r = tid; r < 4 * HD; r += 256) g_bias[r] = b_ih[r] + b_hh[r];
    } else {
        int j0 = (blk - 1) * 128;
        for (int idx = tid; idx < 128 * BB; idx += 256) {
            int j = j0 + (idx >> 6), b = idx & 63;
            g_hT[0][j * BB + b] = h0[(size_t)b * HD + j];
        }
    }
}

// ------------------- x-chain: s_{t+1} = sigmoid(W_in s_t + b_in), 511 steps -------------------
// 8 persistent blocks x 256 threads. Block owns 64 rows of W_in, smem-resident,
// 516-float padded stride (conflict-free). Thread (row=tid&63 within pair-of-warps.. ,
// h2=tid>>6) covers k in [h2*128, +128).
__global__ void __launch_bounds__(256, 1) xchain_kernel(
    const float* __restrict__ W_in, const float* __restrict__ b_in)
{
    extern __shared__ __align__(16) float xs[];
    float* ws   = xs;                 // [64][516]
    float* sS   = xs + 64 * 516;      // [512]
    float* psum = sS + 512;           // [4][64]

    int tid = threadIdx.x, blk = blockIdx.x;
    int row = tid & 63, h2 = tid >> 6;

    for (int e = tid; e < 64 * 512; e += 256) {
        int r = e >> 9, k = e & 511;
        ws[r * 516 + k] = W_in[(size_t)(blk * 64 + r) * 512 + k];
    }
    __syncthreads();

    for (int t = 0; t < SL - 1; ++t) {
        // stage s_t
        const float2* src = (const float2*)(g_Xs + (size_t)t * 512);
        ((float2*)sS)[tid] = __ldcg(&src[tid]);
        __syncthreads();

        float a = 0.f;
        const float* wr = ws + row * 516 + h2 * 128;
        const float* sv = sS + h2 * 128;
        #pragma unroll 8
        for (int i = 0; i < 128; ++i) a = fmaf(wr[i], sv[i], a);
        psum[h2 * 64 + row] = a;
        __syncthreads();

        if (tid < 64) {
            float tot = psum[tid] + psum[64 + tid] + psum[128 + tid] + psum[192 + tid]
                      + b_in[blk * 64 + tid];
            g_Xs[(size_t)(t + 1) * 512 + blk * 64 + tid] = sigm_f(tot);
        }

        if (t != SL - 2) {
            unsigned int tok = (unsigned int)(t + 1);
            __syncthreads();
            if (tid == 0) {
                __threadfence();
                ((volatile unsigned int*)g_xflags)[blk] = tok;
            }
            if (blk == 0) {
                if (tid < XBLK) {
                    while (((volatile unsigned int*)g_xflags)[tid] != tok) { }
                }
                __syncthreads();
                if (tid == 0) { __threadfence(); *((volatile unsigned int*)&g_xgo) = tok; }
            }
            if (tid == 0) {
                while (*((volatile unsigned int*)&g_xgo) != tok) { }
                __threadfence();
            }
            __syncthreads();
        }
    }
}

// ------------------- persistent recurrence chain -------------------
// 128 blocks x 256 threads. Block (g = blk>>2, bgrp = blk&3) owns
//   J-dims [16g, 16g+16) (gate rows q*512+16g+jl, local r = 16q+jl, r in 0..63)
//   batches [16bgrp, +16)
// smem (198656 B): W [0,131072) packed: addr(k,r) = k*256 + ((r&7)>>2)*128
//   + (r>>3)*16 + (r&3)*4;   h [131072,163840): warp kg at +kg*4096, kkl*64+b*4;
//   scratch [163840,198656): warp kg at +kg*4352, b*272 + r*4.
// GEMV thread (kg=tid>>5, rg=(lane>>2), bg=lane&3): rows rg*8..+7, batches bg*4..+3.
__global__ void __launch_bounds__(256, 1) chain_kernel(
    const float* __restrict__ W_hh, const float* __restrict__ c0)
{
    extern __shared__ __align__(16) char smem[];
    char* Hb = smem + 131072;
    char* Sc = smem + 163840;

    const int tid  = threadIdx.x;
    const int blk  = blockIdx.x;
    const int g    = blk >> 2;
    const int bgrp = blk & 3;
    const int kg = tid >> 5, lane = tid & 31;
    const int rg = lane >> 2, bg = lane & 3;

    // ---- one-time: pack W_hh slice (64 rows, non-duplicated) ----
    for (int e = tid; e < 64 * 512; e += 256) {
        int r = e >> 9, k = e & 511;
        int q = r >> 4, jl = r & 15;
        float w = W_hh[(size_t)(q * 512 + g * 16 + jl) * 512 + k];
        *(float*)(smem + k * 256 + ((r & 7) >> 2) * 128 + (r >> 3) * 16 + (r & 3) * 4) = w;
    }
    // c state: one value per thread (jj = tid>>4, bl = tid&15)
    const int jj = tid >> 4, bl = tid & 15;
    const int J = g * 16 + jj, B = bgrp * 16 + bl;
    float cS = c0[(size_t)B * 512 + J];
    __syncthreads();

    char* hb = Hb + kg * 4096;   // warp-private staged h (64 k x 16 b)
    char* sb = Sc + kg * 4352;   // warp-private partial scratch

    for (int t = 0; t < SL; ++t) {
        const float* hsrc = g_hT[t & 1];

        // ---- stage half 0 (kkl 0..31) ----
        float4 v0[4];
        #pragma unroll
        for (int it = 0; it < 4; ++it) {
            int idx = it * 32 + lane;
            int kkl = idx >> 2, b4 = (idx & 3) * 4;
            v0[it] = __ldcg((const float4*)(hsrc + (size_t)(kg * 64 + kkl) * 64
                                            + bgrp * 16 + b4));
        }
        #pragma unroll
        for (int it = 0; it < 4; ++it) {
            int idx = it * 32 + lane;
            int kkl = idx >> 2, b4 = (idx & 3) * 4;
            *(float4*)(hb + kkl * 64 + b4 * 4) = v0[it];
        }
        __syncwarp();

        // ---- issue half-1 loads (kkl 32..63), latency hidden under GEMV half-0 ----
        float4 v1[4];
        #pragma unroll
        for (int it = 0; it < 4; ++it) {
            int idx = it * 32 + lane;
            int kkl = 32 + (idx >> 2), b4 = (idx & 3) * 4;
            v1[it] = __ldcg((const float4*)(hsrc + (size_t)(kg * 64 + kkl) * 64
                                            + bgrp * 16 + b4));
        }

        unsigned long long acc[4][4];   // [row-pair p][batch j]
        #pragma unroll
        for (int p = 0; p < 4; ++p)
            #pragma unroll
            for (int j = 0; j < 4; ++j) acc[p][j] = 0ull;

        // ---- GEMV half 0 ----
        #pragma unroll 4
        for (int kkl = 0; kkl < 32; ++kkl) {
            int k = kg * 64 + kkl;
            float4 hv = *(const float4*)(hb + kkl * 64 + bg * 16);
            unsigned long long hp0 = dup2(hv.x), hp1 = dup2(hv.y);
            unsigned long long hp2 = dup2(hv.z), hp3 = dup2(hv.w);
            ulonglong2 wa = *(const ulonglong2*)(smem + k * 256 + rg * 16);
            ulonglong2 wb = *(const ulonglong2*)(smem + k * 256 + 128 + rg * 16);
            ffma2(acc[0][0], wa.x, hp0); ffma2(acc[1][0], wa.y, hp0);
            ffma2(acc[2][0], wb.x, hp0); ffma2(acc[3][0], wb.y, hp0);
            ffma2(acc[0][1], wa.x, hp1); ffma2(acc[1][1], wa.y, hp1);
            ffma2(acc[2][1], wb.x, hp1); ffma2(acc[3][1], wb.y, hp1);
            ffma2(acc[0][2], wa.x, hp2); ffma2(acc[1][2], wa.y, hp2);
            ffma2(acc[2][2], wb.x, hp2); ffma2(acc[3][2], wb.y, hp2);
            ffma2(acc[0][3], wa.x, hp3); ffma2(acc[1][3], wa.y, hp3);
            ffma2(acc[2][3], wb.x, hp3); ffma2(acc[3][3], wb.y, hp3);
        }

        // ---- store half-1, GEMV half 1 ----
        #pragma unroll
        for (int it = 0; it < 4; ++it) {
            int idx = it * 32 + lane;
            int kkl = 32 + (idx >> 2), b4 = (idx & 3) * 4;
            *(float4*)(hb + kkl * 64 + b4 * 4) = v1[it];
        }
        __syncwarp();
        #pragma unroll 4
        for (int kkl = 32; kkl < 64; ++kkl) {
            int k = kg * 64 + kkl;
            float4 hv = *(const float4*)(hb + kkl * 64 + bg * 16);
            unsigned long long hp0 = dup2(hv.x), hp1 = dup2(hv.y);
            unsigned long long hp2 = dup2(hv.z), hp3 = dup2(hv.w);
            ulonglong2 wa = *(const ulonglong2*)(smem + k * 256 + rg * 16);
            ulonglong2 wb = *(const ulonglong2*)(smem + k * 256 + 128 + rg * 16);
            ffma2(acc[0][0], wa.x, hp0); ffma2(acc[1][0], wa.y, hp0);
            ffma2(acc[2][0], wb.x, hp0); ffma2(acc[3][0], wb.y, hp0);
            ffma2(acc[0][1], wa.x, hp1); ffma2(acc[1][1], wa.y, hp1);
            ffma2(acc[2][1], wb.x, hp1); ffma2(acc[3][1], wb.y, hp1);
            ffma2(acc[0][2], wa.x, hp2); ffma2(acc[1][2], wa.y, hp2);
            ffma2(acc[2][2], wb.x, hp2); ffma2(acc[3][2], wb.y, hp2);
            ffma2(acc[0][3], wa.x, hp3); ffma2(acc[1][3], wa.y, hp3);
            ffma2(acc[2][3], wb.x, hp3); ffma2(acc[3][3], wb.y, hp3);
        }

        // ---- partials to scratch: rows rg*8.., batches bg*4+j ----
        #pragma unroll
        for (int j = 0; j < 4; ++j) {
            int b = bg * 4 + j;
            *(ulonglong2*)(sb + b * 272 + rg * 32)      = make_ulonglong2(acc[0][j], acc[1][j]);
            *(ulonglong2*)(sb + b * 272 + rg * 32 + 16) = make_ulonglong2(acc[2][j], acc[3][j]);
        }
        __syncthreads();

        // ---- reduce over 8 k-chunks + LSTM pointwise (all 256 threads) ----
        {
            float gate[4];
            #pragma unroll
            for (int q = 0; q < 4; ++q) {
                int r = q * 16 + jj;
                float s = 0.f;
                #pragma unroll
                for (int kk = 0; kk < 8; ++kk)
                    s += *(const float*)(Sc + kk * 4352 + bl * 272 + r * 4);
                gate[q] = s + __ldcg(&g_XGall[(size_t)t * 2048 + q * 512 + g * 16 + jj]);
            }
            cS = fmaf(sigm_f(gate[1]), cS, sigm_f(gate[0]) * tanh_f(gate[2]));
            float hN = sigm_f(gate[3]) * tanh_f(cS);
            g_hT[(t + 1) & 1][J * 64 + B] = hN;
            g_Hs[((size_t)t * 64 + B) * 512 + J] = hN;
        }

        // ---- grid barrier (skip last step) ----
        if (t != SL - 1) {
            unsigned int tok = (unsigned int)(t + 1);
            __syncthreads();
            if (tid == 0) {
                __threadfence();
                ((volatile unsigned int*)g_flags)[blk] = tok;
            }
            if (blk == 0) {
                if (tid < NBLK) {
                    while (((volatile unsigned int*)g_flags)[tid] != tok) { }
                }
                __syncthreads();
                if (tid == 0) { __threadfence(); *((volatile unsigned int*)&g_go) = tok; }
            }
            if (tid == 0) {
                while (*((volatile unsigned int*)&g_go) != tok) { }
                __threadfence();
            }
            __syncthreads();
        }
    }
}

// ------------------- SGEMM NT: C[M][cstride] = A[M][512] * W[N][512]^T + bias -------------------
__global__ void __launch_bounds__(256) sgemm_nt(
    const float* __restrict__ A, const float* __restrict__ W,
    const float* __restrict__ bias, float* __restrict__ C, int cstride)
{
    __shared__ __align__(16) float As[8][128];
    __shared__ __align__(16) float Ws[8][128];
    int bm = blockIdx.y << 7, bn = blockIdx.x << 7;
    int tid = threadIdx.x;
    int tx = tid & 15, ty = tid >> 4;
    int lr = tid >> 1, lc = (tid & 1) << 2;

    float acc[8][8];
    #pragma unroll
    for (int i = 0; i < 8; i++)
        #pragma unroll
        for (int j = 0; j < 8; j++) acc[i][j] = 0.f;

    for (int k0 = 0; k0 < 512; k0 += 8) {
        float4 av = *(const float4*)&A[(size_t)(bm + lr) * 512 + k0 + lc];
        float4 wv = *(const float4*)&W[(size_t)(bn + lr) * 512 + k0 + lc];
        As[lc + 0][lr] = av.x; As[lc + 1][lr] = av.y;
        As[lc + 2][lr] = av.z; As[lc + 3][lr] = av.w;
        Ws[lc + 0][lr] = wv.x; Ws[lc + 1][lr] = wv.y;
        Ws[lc + 2][lr] = wv.z; Ws[lc + 3][lr] = wv.w;
        __syncthreads();
        #pragma unroll
        for (int kk = 0; kk < 8; kk++) {
            float a[8], bb[8];
            *(float4*)&a[0]  = *(const float4*)&As[kk][ty * 8];
            *(float4*)&a[4]  = *(const float4*)&As[kk][ty * 8 + 4];
            *(float4*)&bb[0] = *(const float4*)&Ws[kk][tx * 8];
            *(float4*)&bb[4] = *(const float4*)&Ws[kk][tx * 8 + 4];
            #pragma unroll
            for (int i = 0; i < 8; i++)
                #pragma unroll
                for (int j = 0; j < 8; j++)
                    acc[i][j] = fmaf(a[i], bb[j], acc[i][j]);
        }
        __syncthreads();
    }
    #pragma unroll
    for (int i = 0; i < 8; i++) {
        size_t off = (size_t)(bm + ty * 8 + i) * cstride + bn + tx * 8;
        #pragma unroll
        for (int j = 0; j < 8; j++)
            C[off + j] = acc[i][j] + bias[bn + tx * 8 + j];
    }
}

// ------------------- attention: u[b,t,s] = tanh(K1[b,s,:]+Q[t,b,:]) . v + b_v -------------------
__global__ void __launch_bounds__(1024) attn_kernel(
    const float* __restrict__ v, const float* __restrict__ b_v,
    const unsigned int* __restrict__ mask32, float* __restrict__ out)
{
    __shared__ float Ksh[32][65];
    __shared__ float Qsh[32][65];
    __shared__ float vsh[64];
    int b  = blockIdx.z;
    int t0 = blockIdx.y << 5;
    int s0 = blockIdx.x << 5;
    int tid = threadIdx.x;
    int sl = tid & 31, tl = tid >> 5;

    float acc = 0.f;
    for (int h0 = 0; h0 < 512; h0 += 64) {
        if (tid < 64) vsh[tid] = v[h0 + tid];
        #pragma unroll
        for (int i = 0; i < 2; i++) {
            int id = tid + i * 1024;
            int row = id >> 6, cc = id & 63;
            Ksh[row][cc] = g_K1[((size_t)b * 512 + s0 + row) * 512 + h0 + cc];
            Qsh[row][cc] = g_Q[((size_t)(t0 + row) * 64 + b) * 512 + h0 + cc];
        }
        __syncthreads();
        #pragma unroll
        for (int h = 0; h < 64; h++) {
            float x = Ksh[sl][h] + Qsh[tl][h];
            acc = fmaf(tanh_f(x), vsh[h], acc);
        }
        __syncthreads();
    }
    float u = acc + b_v[0];
    int s = s0 + sl;
    if (mask32[b * 512 + s] == 0u) u = -1e9f;
    out[((size_t)b * 512 + t0 + tl) * 512 + s] = u;
}

// ------------------- argmax over last dim (first-max tie rule) -------------------
__global__ void __launch_bounds__(256) argmax_kernel(
    const float* __restrict__ logits, float* __restrict__ outf,
    int* __restrict__ outi, int as_float)
{
    int row = blockIdx.x * 8 + (threadIdx.x >> 5);
    int lane = threadIdx.x & 31;
    const float* p = logits + (size_t)row * 512;
    float best = -INFINITY; int bi = 0;
    for (int s = lane; s < 512; s += 32) {
        float vv = p[s];
        if (vv > best) { best = vv; bi = s; }
    }
    #pragma unroll
    for (int off = 16; off; off >>= 1) {
        float ov = __shfl_down_sync(0xffffffffu, best, off);
        int   oi = __shfl_down_sync(0xffffffffu, bi,   off);
        if (ov > best || (ov == best && oi < bi)) { best = ov; bi = oi; }
    }
    if (lane == 0) {
        if (as_float) outf[row] = (float)bi;
        else          outi[row] = bi;
    }
}

// ------------------- launcher -------------------
extern "C" void kernel_launch(void* const* d_in, const int* in_sizes, int n_in,
                              void* d_out, int out_size) {
    const float* enc  = (const float*)d_in[0];
    const unsigned int* mask32 = (const unsigned int*)d_in[1];
    const float* h0   = (const float*)d_in[2];
    const float* c0   = (const float*)d_in[3];
    const float* W_in = (const float*)d_in[4];
    const float* b_in = (const float*)d_in[5];
    const float* W_ih = (const float*)d_in[6];
    const float* b_ih = (const float*)d_in[7];
    const float* W_hh = (const float*)d_in[8];
    const float* b_hh = (const float*)d_in[9];
    const float* W1   = (const float*)d_in[10];
    const float* b1   = (const float*)d_in[11];
    const float* W2   = (const float*)d_in[12];
    const float* b2   = (const float*)d_in[13];
    const float* v    = (const float*)d_in[14];
    const float* b_v  = (const float*)d_in[15];
    (void)in_sizes; (void)n_in;

    float *pK1, *pQ, *pHs, *pL, *pXs, *pXG, *pBias;
    cudaGetSymbolAddress((void**)&pK1,  g_K1);
    cudaGetSymbolAddress((void**)&pQ,   g_Q);
    cudaGetSymbolAddress((void**)&pHs,  g_Hs);
    cudaGetSymbolAddress((void**)&pL,   g_L);
    cudaGetSymbolAddress((void**)&pXs,  g_Xs);
    cudaGetSymbolAddress((void**)&pXG,  g_XGall);
    cudaGetSymbolAddress((void**)&pBias, g_bias);

    const int CHAIN_SMEM = 198656;
    const int XCH_SMEM   = 64 * 516 * 4 + 512 * 4 + 4 * 64 * 4;  // 135168
    cudaFuncSetAttribute(chain_kernel,
                         cudaFuncAttributeMaxDynamicSharedMemorySize, CHAIN_SMEM);
    cudaFuncSetAttribute(xchain_kernel,
                         cudaFuncAttributeMaxDynamicSharedMemorySize, XCH_SMEM);

    prologue_kernel<<<5, 256>>>(h0, b_in, b_ih, b_hh);
    xchain_kernel<<<XBLK, 256, XCH_SMEM>>>(W_in, b_in);
    sgemm_nt<<<dim3(4, 256), 256>>>(enc, W1, b1, pK1, 512);      // K1
    sgemm_nt<<<dim3(16, 4), 256>>>(pXs, W_ih, pBias, pXG, 2048); // XGall

    chain_kernel<<<NBLK, 256, CHAIN_SMEM>>>(W_hh, c0);

    sgemm_nt<<<dim3(4, 256), 256>>>(pHs, W2, b2, pQ, 512);       // Q

    const long long NL = (long long)BB * SL * SL;                // 16,777,216
    float* ldst = ((long long)out_size >= NL) ? (float*)d_out : pL;
    attn_kernel<<<dim3(16, 16, 64), 1024>>>(v, b_v, mask32, ldst);

    if ((long long)out_size >= NL + BB * SL) {
        argmax_kernel<<<4096, 256>>>(ldst, (float*)d_out + NL, nullptr, 1);
    } else if ((long long)out_size < NL) {
        argmax_kernel<<<4096, 256>>>(ldst, nullptr, (int*)d_out, 0);
    }
}

// round 9
// speedup vs baseline: 1.1865x; 1.1865x over previous
#include <cuda_runtime.h>
#include <math.h>

// Problem constants
static const int BB = 64;    // batch
static const int SL = 512;   // sequence length
static const int HD = 512;   // hidden
static const int G4 = 2048;  // 4*H gates
#define NBLK 128             // persistent blocks (<=148 SMs -> all resident)

// 2*log2(e): pre-scale for attention logit args so exp(2x) == ex2(x')
#define ATTN_SCALE 2.8853900817779268f

// ------------------- device scratch (no allocations allowed) -------------------
__device__ float g_K1[(size_t)BB * SL * HD];   // key projection (pre-scaled), row = b*SL+s
__device__ float g_Q [(size_t)SL * BB * HD];   // query (pre-scaled),          row = t*BB+b
__device__ float g_Hs[(size_t)SL * BB * HD];   // h sequence,     row = t*BB+b
__device__ float g_hT[2][HD * BB];             // transposed h (double buffer) [j][b]
__device__ float g_Xu[2][HD];                  // x' chain (batch independent)
__device__ float g_XG[2][G4];                  // XG[t] = Xu[t]@W_ih^T + b_ih + b_hh
__device__ float g_Sv;                         // sum(v) + b_v
__device__ float g_L [(size_t)BB * SL * SL];   // logits fallback scratch

// flag-array grid barrier (no atomics). Equality-compared monotonic tokens;
// last-step barrier skipped -> replay-safe.
__device__ unsigned int g_flags[NBLK];
__device__ unsigned int g_go;

// ------------------- accurate fast activations (flag-independent) -------------------
__device__ __forceinline__ float sigm_f(float x) {
    float e = __expf(-x);
    return __fdividef(1.0f, 1.0f + e);
}
__device__ __forceinline__ float tanh_f(float x) {
    float e = __expf(2.0f * x);
    return 1.0f - __fdividef(2.0f, e + 1.0f);
}
__device__ __forceinline__ float ex2f(float x) {
    float r; asm("ex2.approx.f32 %0, %1;" : "=f"(r) : "f"(x)); return r;
}
__device__ __forceinline__ float rcpf(float x) {
    float r; asm("rcp.approx.f32 %0, %1;" : "=f"(r) : "f"(x)); return r;
}

// packed fp32x2 FMA (FFMA2) -- PTX-only
__device__ __forceinline__ void ffma2(unsigned long long& d, unsigned long long a,
                                      unsigned long long b) {
    asm("fma.rn.f32x2 %0, %1, %2, %0;" : "+l"(d) : "l"(a), "l"(b));
}

// device-wide barrier, token-based
__device__ __forceinline__ void grid_barrier_tok(unsigned int tok) {
    __syncthreads();
    if (threadIdx.x == 0) {
        __threadfence();
        ((volatile unsigned int*)g_flags)[blockIdx.x] = tok;
    }
    if (blockIdx.x == 0) {
        if (threadIdx.x < NBLK) {
            while (((volatile unsigned int*)g_flags)[threadIdx.x] != tok) { }
        }
        __syncthreads();
        if (threadIdx.x == 0) { __threadfence(); *((volatile unsigned int*)&g_go) = tok; }
    }
    if (threadIdx.x == 0) {
        while (*((volatile unsigned int*)&g_go) != tok) { }
        __threadfence();
    }
    __syncthreads();
}

// ------------------- prologue: Xu[0], Xu[1], XG[0], transpose h0, Sv -------------------
__global__ void __launch_bounds__(256) prologue_kernel(
    const float* __restrict__ h0,
    const float* __restrict__ W_in, const float* __restrict__ b_in,
    const float* __restrict__ W_ih, const float* __restrict__ b_ih,
    const float* __restrict__ b_hh,
    const float* __restrict__ v,    const float* __restrict__ b_v)
{
    int blk = blockIdx.x, tid = threadIdx.x;
    if (blk == 0) {
        __shared__ float x0s[HD];
        for (int i = tid; i < HD; i += 256) {
            float x = sigm_f(b_in[i]);
            x0s[i] = x;
            g_Xu[0][i] = x;
        }
        __syncthreads();
        for (int row = tid; row < HD; row += 256) {
            float acc = b_in[row];
            const float* wr = W_in + (size_t)row * HD;
            for (int k = 0; k < HD; k += 4) {
                float4 w4 = *(const float4*)&wr[k];
                acc = fmaf(x0s[k+0], w4.x, acc);
                acc = fmaf(x0s[k+1], w4.y, acc);
                acc = fmaf(x0s[k+2], w4.z, acc);
                acc = fmaf(x0s[k+3], w4.w, acc);
            }
            g_Xu[1][row] = sigm_f(acc);
        }
    } else if (blk <= 16) {
        __shared__ float x0s[HD];
        for (int i = tid; i < HD; i += 256) x0s[i] = sigm_f(b_in[i]);
        __syncthreads();
        if (tid < 128) {
            int row = (blk - 1) * 128 + tid;
            float acc = b_ih[row] + b_hh[row];
            const float* wr = W_ih + (size_t)row * HD;
            for (int k = 0; k < HD; k += 4) {
                float4 w4 = *(const float4*)&wr[k];
                acc = fmaf(x0s[k+0], w4.x, acc);
                acc = fmaf(x0s[k+1], w4.y, acc);
                acc = fmaf(x0s[k+2], w4.z, acc);
                acc = fmaf(x0s[k+3], w4.w, acc);
            }
            g_XG[0][row] = acc;
        }
    } else if (blk <= 20) {
        int j0 = (blk - 17) * 128;
        for (int idx = tid; idx < 128 * BB; idx += 256) {
            int j = j0 + (idx >> 6), b = idx & 63;
            g_hT[0][j * BB + b] = h0[(size_t)b * HD + j];
        }
    } else {
        // Sv = sum(v) + b_v
        __shared__ float red[256];
        float s = v[tid] + v[tid + 256];
        red[tid] = s;
        __syncthreads();
        for (int off = 128; off; off >>= 1) {
            if (tid < off) red[tid] += red[tid + off];
            __syncthreads();
        }
        if (tid == 0) g_Sv = red[0] + b_v[0];
    }
}

// ------------------- persistent recurrence chain (R6 layout, known-good) -------------------
__global__ void __launch_bounds__(256, 1) chain_kernel(
    const float* __restrict__ W_hh, const float* __restrict__ W_ih,
    const float* __restrict__ W_in, const float* __restrict__ b_in,
    const float* __restrict__ b_ih, const float* __restrict__ b_hh,
    const float* __restrict__ c0)
{
    extern __shared__ __align__(16) char smem[];
    char*  Hbase = smem + 131072;
    float* XuS   = (float*)(smem + 196608);

    const int tid  = threadIdx.x;
    const int blk  = blockIdx.x;
    const int g    = blk >> 1;
    const int bgrp = blk & 1;
    const int kg = tid >> 5, lane = tid & 31;
    const int rg = (tid >> 3) & 3, bg = tid & 7;

    for (int e = tid; e < 32 * 512; e += 256) {
        int r = e >> 9, k = e & 511;
        int q = r >> 3, jl = r & 7;
        float w = W_hh[(size_t)(q * 512 + g * 8 + jl) * 512 + k];
        *(float2*)(smem + k * 256 + (jl >> 1) * 64 + q * 16 + (jl & 1) * 8)
            = make_float2(w, w);
    }
    float cA = 0.f, cB = 0.f;
    int J = 0, B0 = 0;
    if (tid < 128) {
        J  = g * 8 + (tid >> 4);
        B0 = bgrp * 32 + (tid & 15) * 2;
        cA = c0[(size_t)B0 * 512 + J];
        cB = c0[(size_t)(B0 + 1) * 512 + J];
    }
    __syncthreads();

    char* hb = Hbase + kg * 8192;

    for (int t = 0; t < SL; ++t) {
        {
            const float2* xsrc = (const float2*)g_Xu[(t + 1) & 1];
            ((float2*)XuS)[tid] = __ldcg(&xsrc[tid]);
        }
        {
            const float* hsrc = g_hT[t & 1];
            #pragma unroll
            for (int it = 0; it < 16; ++it) {
                int idx = lane + 32 * it;
                int kkl = idx >> 3, b4 = (idx & 7) * 4;
                float4 v4 = __ldcg((const float4*)(hsrc
                              + (size_t)(kg * 64 + kkl) * 64 + bgrp * 32 + b4));
                *(float4*)(hb + kkl * 128 + b4 * 4) = v4;
            }
        }
        __syncwarp();

        unsigned long long acc[8][2];
        #pragma unroll
        for (int jl = 0; jl < 8; ++jl) { acc[jl][0] = 0ull; acc[jl][1] = 0ull; }

        const char* wk = smem + kg * 64 * 256 + rg * 16;
        #pragma unroll 4
        for (int kkl = 0; kkl < 64; ++kkl) {
            ulonglong2 hp = *(const ulonglong2*)(hb + kkl * 128 + bg * 16);
            const char* wr = wk + kkl * 256;
            #pragma unroll
            for (int i = 0; i < 4; ++i) {
                ulonglong2 wp = *(const ulonglong2*)(wr + i * 64);
                ffma2(acc[2*i  ][0], wp.x, hp.x);
                ffma2(acc[2*i  ][1], wp.x, hp.y);
                ffma2(acc[2*i+1][0], wp.y, hp.x);
                ffma2(acc[2*i+1][1], wp.y, hp.y);
            }
        }
        __syncwarp();
        #pragma unroll
        for (int jl = 0; jl < 8; ++jl) {
            int r = rg * 8 + jl;
            *(ulonglong2*)(hb + (r * 16 + bg * 2) * 8)
                = make_ulonglong2(acc[jl][0], acc[jl][1]);
        }
        __syncthreads();

        if (tid < 128) {
            int jl = tid >> 4, bp = tid & 15;
            float2 gate[4];
            #pragma unroll
            for (int q = 0; q < 4; ++q) {
                int r = q * 8 + jl;
                float sx = 0.f, sy = 0.f;
                #pragma unroll
                for (int kk = 0; kk < 8; ++kk) {
                    float2 p = *(const float2*)(Hbase + kk * 8192 + (r * 16 + bp) * 8);
                    sx += p.x; sy += p.y;
                }
                float xg = __ldcg(&g_XG[t & 1][q * 512 + g * 8 + jl]);
                gate[q] = make_float2(sx + xg, sy + xg);
            }
            cA = fmaf(sigm_f(gate[1].x), cA, sigm_f(gate[0].x) * tanh_f(gate[2].x));
            cB = fmaf(sigm_f(gate[1].y), cB, sigm_f(gate[0].y) * tanh_f(gate[2].y));
            float hA = sigm_f(gate[3].x) * tanh_f(cA);
            float hB = sigm_f(gate[3].y) * tanh_f(cB);
            *(float2*)(g_hT[(t + 1) & 1] + (size_t)J * 64 + B0) = make_float2(hA, hB);
            g_Hs[((size_t)t * 64 + B0) * 512 + J]     = hA;
            g_Hs[((size_t)t * 64 + B0 + 1) * 512 + J] = hB;
        } else {
            int grp = (tid - 128) >> 2;
            int l4  = tid & 3;
            int valid = (grp < 20);
            int R = blk * 20 + (valid ? grp : 0);
            const float* w = (R < 2048) ? (W_ih + (size_t)R * 512)
                                        : (W_in + (size_t)(R - 2048) * 512);
            float a = 0.f;
            #pragma unroll
            for (int i = 0; i < 32; ++i) {
                int k0 = i * 16 + l4 * 4;
                float4 wv = __ldg((const float4*)(w + k0));
                float4 xv = *(const float4*)(XuS + k0);
                a = fmaf(wv.x, xv.x, a); a = fmaf(wv.y, xv.y, a);
                a = fmaf(wv.z, xv.z, a); a = fmaf(wv.w, xv.w, a);
            }
            a += __shfl_down_sync(0xffffffffu, a, 2, 4);
            a += __shfl_down_sync(0xffffffffu, a, 1, 4);
            if (valid && l4 == 0) {
                if (R < 2048) g_XG[(t + 1) & 1][R] = a + b_ih[R] + b_hh[R];
                else          g_Xu[t & 1][R - 2048] = sigm_f(a + b_in[R - 2048]);
            }
        }
        if (t != SL - 1) grid_barrier_tok((unsigned int)(t + 1));
    }
}

// ------------------- SGEMM NT: C = scale*(A W^T + bias) -------------------
__global__ void __launch_bounds__(256) sgemm_nt(
    const float* __restrict__ A, const float* __restrict__ W,
    const float* __restrict__ bias, float* __restrict__ C, float scale)
{
    __shared__ __align__(16) float As[8][128];
    __shared__ __align__(16) float Ws[8][128];
    int bm = blockIdx.y << 7, bn = blockIdx.x << 7;
    int tid = threadIdx.x;
    int tx = tid & 15, ty = tid >> 4;
    int lr = tid >> 1, lc = (tid & 1) << 2;

    float acc[8][8];
    #pragma unroll
    for (int i = 0; i < 8; i++)
        #pragma unroll
        for (int j = 0; j < 8; j++) acc[i][j] = 0.f;

    for (int k0 = 0; k0 < 512; k0 += 8) {
        float4 av = *(const float4*)&A[(size_t)(bm + lr) * 512 + k0 + lc];
        float4 wv = *(const float4*)&W[(size_t)(bn + lr) * 512 + k0 + lc];
        As[lc + 0][lr] = av.x; As[lc + 1][lr] = av.y;
        As[lc + 2][lr] = av.z; As[lc + 3][lr] = av.w;
        Ws[lc + 0][lr] = wv.x; Ws[lc + 1][lr] = wv.y;
        Ws[lc + 2][lr] = wv.z; Ws[lc + 3][lr] = wv.w;
        __syncthreads();
        #pragma unroll
        for (int kk = 0; kk < 8; kk++) {
            float a[8], bb[8];
            *(float4*)&a[0]  = *(const float4*)&As[kk][ty * 8];
            *(float4*)&a[4]  = *(const float4*)&As[kk][ty * 8 + 4];
            *(float4*)&bb[0] = *(const float4*)&Ws[kk][tx * 8];
            *(float4*)&bb[4] = *(const float4*)&Ws[kk][tx * 8 + 4];
            #pragma unroll
            for (int i = 0; i < 8; i++)
                #pragma unroll
                for (int j = 0; j < 8; j++)
                    acc[i][j] = fmaf(a[i], bb[j], acc[i][j]);
        }
        __syncthreads();
    }
    #pragma unroll
    for (int i = 0; i < 8; i++) {
        size_t off = (size_t)(bm + ty * 8 + i) * 512 + bn + tx * 8;
        #pragma unroll
        for (int j = 0; j < 8; j++)
            C[off + j] = scale * (acc[i][j] + bias[bn + tx * 8 + j]);
    }
}

// ------------------- attention (4-way grouped rational) -------------------
// K1,Q are pre-scaled by 2*log2(e): tanh contribution v_i*(1 - 2/(2^{x'_i}+1)).
// u = Sv - 2 * sum over groups-of-4 of N/D with common denominator.
__global__ void __launch_bounds__(1024) attn_kernel(
    const float* __restrict__ v,
    const unsigned int* __restrict__ mask32, float* __restrict__ out)
{
    __shared__ float Ksh[32][68];
    __shared__ float Qsh[32][68];
    __shared__ __align__(16) float vsh[64];
    int b  = blockIdx.z;
    int t0 = blockIdx.y << 5;
    int s0 = blockIdx.x << 5;
    int tid = threadIdx.x;
    int sl = tid & 31, tl = tid >> 5;

    float acc = 0.f;
    for (int h0 = 0; h0 < 512; h0 += 64) {
        if (tid < 64) vsh[tid] = v[h0 + tid];
        #pragma unroll
        for (int i = 0; i < 2; i++) {
            int id = tid + i * 1024;
            int row = id >> 6, cc = id & 63;
            Ksh[row][cc] = g_K1[((size_t)b * 512 + s0 + row) * 512 + h0 + cc];
            Qsh[row][cc] = g_Q[((size_t)(t0 + row) * 64 + b) * 512 + h0 + cc];
        }
        __syncthreads();
        #pragma unroll
        for (int hh = 0; hh < 64; hh += 4) {
            float4 kv = *(const float4*)&Ksh[sl][hh];
            float4 qv = *(const float4*)&Qsh[tl][hh];
            float4 vv = *(const float4*)&vsh[hh];
            // clamp x' <= 23 (tanh(arg>~8) == 1 to 2.3e-7)
            float x0 = fminf(kv.x + qv.x, 23.0f);
            float x1 = fminf(kv.y + qv.y, 23.0f);
            float x2 = fminf(kv.z + qv.z, 23.0f);
            float x3 = fminf(kv.w + qv.w, 23.0f);
            float d0 = ex2f(x0) + 1.0f;
            float d1 = ex2f(x1) + 1.0f;
            float d2 = ex2f(x2) + 1.0f;
            float d3 = ex2f(x3) + 1.0f;
            float d01 = d0 * d1, d23 = d2 * d3;
            float n01 = fmaf(vv.x, d1, vv.y * d0);
            float n23 = fmaf(vv.z, d3, vv.w * d2);
            float N   = fmaf(n01, d23, n23 * d01);
            float D   = d01 * d23;
            acc = fmaf(N, rcpf(D), acc);
        }
        __syncthreads();
    }
    float u = g_Sv - 2.0f * acc;
    int s = s0 + sl;
    if (mask32[b * 512 + s] == 0u) u = -1e9f;
    out[((size_t)b * 512 + t0 + tl) * 512 + s] = u;
}

// ------------------- argmax over last dim (first-max tie rule) -------------------
__global__ void __launch_bounds__(256) argmax_kernel(
    const float* __restrict__ logits, float* __restrict__ outf,
    int* __restrict__ outi, int as_float)
{
    int row = blockIdx.x * 8 + (threadIdx.x >> 5);
    int lane = threadIdx.x & 31;
    const float* p = logits + (size_t)row * 512;
    float best = -INFINITY; int bi = 0;
    for (int s = lane; s < 512; s += 32) {
        float vv = p[s];
        if (vv > best) { best = vv; bi = s; }
    }
    #pragma unroll
    for (int off = 16; off; off >>= 1) {
        float ov = __shfl_down_sync(0xffffffffu, best, off);
        int   oi = __shfl_down_sync(0xffffffffu, bi,   off);
        if (ov > best || (ov == best && oi < bi)) { best = ov; bi = oi; }
    }
    if (lane == 0) {
        if (as_float) outf[row] = (float)bi;
        else          outi[row] = bi;
    }
}

// ------------------- launcher -------------------
extern "C" void kernel_launch(void* const* d_in, const int* in_sizes, int n_in,
                              void* d_out, int out_size) {
    const float* enc  = (const float*)d_in[0];
    const unsigned int* mask32 = (const unsigned int*)d_in[1];
    const float* h0   = (const float*)d_in[2];
    const float* c0   = (const float*)d_in[3];
    const float* W_in = (const float*)d_in[4];
    const float* b_in = (const float*)d_in[5];
    const float* W_ih = (const float*)d_in[6];
    const float* b_ih = (const float*)d_in[7];
    const float* W_hh = (const float*)d_in[8];
    const float* b_hh = (const float*)d_in[9];
    const float* W1   = (const float*)d_in[10];
    const float* b1   = (const float*)d_in[11];
    const float* W2   = (const float*)d_in[12];
    const float* b2   = (const float*)d_in[13];
    const float* v    = (const float*)d_in[14];
    const float* b_v  = (const float*)d_in[15];
    (void)in_sizes; (void)n_in;

    float *pK1, *pQ, *pHs, *pL;
    cudaGetSymbolAddress((void**)&pK1, g_K1);
    cudaGetSymbolAddress((void**)&pQ,  g_Q);
    cudaGetSymbolAddress((void**)&pHs, g_Hs);
    cudaGetSymbolAddress((void**)&pL,  g_L);

    const int CHAIN_SMEM = 198656;
    cudaFuncSetAttribute(chain_kernel,
                         cudaFuncAttributeMaxDynamicSharedMemorySize, CHAIN_SMEM);

    prologue_kernel<<<22, 256>>>(h0, W_in, b_in, W_ih, b_ih, b_hh, v, b_v);
    sgemm_nt<<<dim3(4, 256), 256>>>(enc, W1, b1, pK1, ATTN_SCALE);   // K1 (pre-scaled)

    chain_kernel<<<NBLK, 256, CHAIN_SMEM>>>(W_hh, W_ih, W_in, b_in, b_ih, b_hh, c0);

    sgemm_nt<<<dim3(4, 256), 256>>>(pHs, W2, b2, pQ, ATTN_SCALE);    // Q (pre-scaled)

    const long long NL = (long long)BB * SL * SL;                    // 16,777,216
    float* ldst = ((long long)out_size >= NL) ? (float*)d_out : pL;
    attn_kernel<<<dim3(16, 16, 64), 1024>>>(v, mask32, ldst);

    if ((long long)out_size >= NL + BB * SL) {
        argmax_kernel<<<4096, 256>>>(ldst, (float*)d_out + NL, nullptr, 1);
    } else if ((long long)out_size < NL) {
        argmax_kernel<<<4096, 256>>>(ldst, nullptr, (int*)d_out, 0);
    }
}